// round 5
// baseline (speedup 1.0000x reference)
#include <cuda_runtime.h>
#include <cuda_bf16.h>
#include <math.h>
#include <stdint.h>

#define DI __device__ __forceinline__

namespace {
constexpr int Bn = 16;
constexpr int Sn = 2048;
constexpr int Hn = 128;
constexpr int Dn = 64;
constexpr float SHIFT = 20.0f;
constexpr int NPAD = 136;       // padded n-dim (64 Q | 64 K | u | pad)
constexpr int QKS = 72;         // smem stride for 64-wide bf16 tiles
}

// Scratch (no device mallocs allowed)
__device__ __nv_bfloat16 g_Wh[NPAD * Hn];      // fused weight hi, [n][h]
__device__ __nv_bfloat16 g_Wl[NPAD * Hn];      // fused weight lo
__device__ float         g_PE[Sn * Hn];
__device__ __nv_bfloat16 g_Qh[Bn * Sn * Dn];   // Q/8 hi
__device__ __nv_bfloat16 g_Ql[Bn * Sn * Dn];   // Q/8 lo
__device__ __nv_bfloat16 g_Kh[Bn * Sn * Dn];
__device__ __nv_bfloat16 g_Kl[Bn * Sn * Dn];
__device__ float         g_u[Bn * Sn];         // xp @ (Wv @ Wf)
__device__ float         g_t[Bn * Sn];         // u / Z

DI uint32_t ld32(const __nv_bfloat16* p) { return *(const uint32_t*)p; }

DI void mma_bf16(float* c, uint32_t a0, uint32_t a1, uint32_t a2, uint32_t a3,
                 uint32_t b0, uint32_t b1) {
    asm volatile(
        "mma.sync.aligned.m16n8k16.row.col.f32.bf16.bf16.f32 "
        "{%0,%1,%2,%3}, {%4,%5,%6,%7}, {%8,%9}, {%0,%1,%2,%3};\n"
        : "+f"(c[0]), "+f"(c[1]), "+f"(c[2]), "+f"(c[3])
        : "r"(a0), "r"(a1), "r"(a2), "r"(a3), "r"(b0), "r"(b1));
}

// split a pair of fp32 into hi/lo bf16x2
DI void split2(float a, float b, __nv_bfloat162* hd, __nv_bfloat162* ld) {
    __nv_bfloat162 h = __floats2bfloat162_rn(a, b);
    float ra = a - __low2float(h);
    float rb = b - __high2float(h);
    *hd = h;
    *ld = __floats2bfloat162_rn(ra, rb);
}

// ---------------- K0a: sinusoidal positional encoding table ----------------
__global__ void k_pe() {
    int idx = blockIdx.x * blockDim.x + threadIdx.x;
    if (idx >= Sn * (Hn / 2)) return;
    int p = idx >> 6;
    int j = idx & 63;
    double fac = pow(10000.0, (double)j / 64.0);
    float ang = (float)((double)p / fac);
    float sv, cv;
    sincosf(ang, &sv, &cv);
    g_PE[p * Hn + 2 * j]     = sv;
    g_PE[p * Hn + 2 * j + 1] = cv;
}

// ---------------- K0b: fused transposed weight, bf16 hi/lo ----------------
__global__ void k_wcat(const float* __restrict__ Wq, const float* __restrict__ Wk,
                       const float* __restrict__ Wv, const float* __restrict__ Wf) {
    int idx = blockIdx.x * blockDim.x + threadIdx.x;
    if (idx >= NPAD * Hn) return;
    int n = idx >> 7;
    int h = idx & 127;
    float v = 0.0f;
    if (n < 64) {
        v = Wq[h * Dn + n] * 0.125f;           // fold 1/sqrt(D)
    } else if (n < 128) {
        v = Wk[h * Dn + (n - 64)];
    } else if (n == 128) {
        float s = 0.0f;
        for (int d = 0; d < Dn; ++d) s += Wv[h * Dn + d] * Wf[d];
        v = s;
    }
    __nv_bfloat16 hb = __float2bfloat16(v);
    g_Wh[n * Hn + h] = hb;
    g_Wl[n * Hn + h] = __float2bfloat16(v - __bfloat162float(hb));
}

// ---------------- K1: xp = x + PE; Q,K (hi/lo) and u via split-mma GEMM ----------------
__global__ void k_qku(const float* __restrict__ x) {
    extern __shared__ __nv_bfloat16 sm[];
    __nv_bfloat16* Ash = sm;                         // [128][stride NPAD]
    __nv_bfloat16* Asl = Ash + 128 * NPAD;
    __nv_bfloat16* Bsh = Asl + 128 * NPAD;           // [NPAD rows][stride NPAD]
    __nv_bfloat16* Bsl = Bsh + NPAD * NPAD;

    int tid = threadIdx.x;
    int r0 = blockIdx.x * 128;
    int srow0 = r0 & (Sn - 1);

    const float4* x4 = (const float4*)x;
    for (int i = tid; i < 128 * 32; i += 256) {
        int row = i >> 5, c4 = i & 31;
        float4 v = x4[(size_t)(r0 + row) * 32 + c4];
        const float* pe = &g_PE[(srow0 + row) * Hn + c4 * 4];
        v.x += pe[0]; v.y += pe[1]; v.z += pe[2]; v.w += pe[3];
        __nv_bfloat162* dh = (__nv_bfloat162*)&Ash[row * NPAD + c4 * 4];
        __nv_bfloat162* dl = (__nv_bfloat162*)&Asl[row * NPAD + c4 * 4];
        split2(v.x, v.y, &dh[0], &dl[0]);
        split2(v.z, v.w, &dh[1], &dl[1]);
    }
    for (int i = tid; i < NPAD * Hn; i += 256) {
        int n = i >> 7, h = i & 127;
        Bsh[n * NPAD + h] = g_Wh[i];
        Bsl[n * NPAD + h] = g_Wl[i];
    }
    __syncthreads();

    int warp = tid >> 5, lane = tid & 31;
    int g = lane >> 2, t = lane & 3;
    int rw = warp * 16;

    float acc[17][4];
#pragma unroll
    for (int nt = 0; nt < 17; nt++)
#pragma unroll
        for (int i = 0; i < 4; i++) acc[nt][i] = 0.0f;

#pragma unroll
    for (int ks = 0; ks < 8; ks++) {
        int kb = ks * 16;
        uint32_t ah0 = ld32(&Ash[(rw + g) * NPAD + kb + 2 * t]);
        uint32_t ah1 = ld32(&Ash[(rw + g + 8) * NPAD + kb + 2 * t]);
        uint32_t ah2 = ld32(&Ash[(rw + g) * NPAD + kb + 2 * t + 8]);
        uint32_t ah3 = ld32(&Ash[(rw + g + 8) * NPAD + kb + 2 * t + 8]);
        uint32_t al0 = ld32(&Asl[(rw + g) * NPAD + kb + 2 * t]);
        uint32_t al1 = ld32(&Asl[(rw + g + 8) * NPAD + kb + 2 * t]);
        uint32_t al2 = ld32(&Asl[(rw + g) * NPAD + kb + 2 * t + 8]);
        uint32_t al3 = ld32(&Asl[(rw + g + 8) * NPAD + kb + 2 * t + 8]);
#pragma unroll
        for (int nt = 0; nt < 17; nt++) {
            uint32_t bh0 = ld32(&Bsh[(nt * 8 + g) * NPAD + kb + 2 * t]);
            uint32_t bh1 = ld32(&Bsh[(nt * 8 + g) * NPAD + kb + 2 * t + 8]);
            uint32_t bl0 = ld32(&Bsl[(nt * 8 + g) * NPAD + kb + 2 * t]);
            uint32_t bl1 = ld32(&Bsl[(nt * 8 + g) * NPAD + kb + 2 * t + 8]);
            mma_bf16(acc[nt], ah0, ah1, ah2, ah3, bh0, bh1);
            mma_bf16(acc[nt], ah0, ah1, ah2, ah3, bl0, bl1);
            mma_bf16(acc[nt], al0, al1, al2, al3, bh0, bh1);
        }
    }

    int rA = r0 + rw + g, rB = rA + 8;
#pragma unroll
    for (int nt = 0; nt < 17; nt++) {
        int col = nt * 8 + 2 * t;
        if (col < 64) {
            split2(acc[nt][0], acc[nt][1],
                   (__nv_bfloat162*)&g_Qh[(size_t)rA * Dn + col],
                   (__nv_bfloat162*)&g_Ql[(size_t)rA * Dn + col]);
            split2(acc[nt][2], acc[nt][3],
                   (__nv_bfloat162*)&g_Qh[(size_t)rB * Dn + col],
                   (__nv_bfloat162*)&g_Ql[(size_t)rB * Dn + col]);
        } else if (col < 128) {
            split2(acc[nt][0], acc[nt][1],
                   (__nv_bfloat162*)&g_Kh[(size_t)rA * Dn + col - 64],
                   (__nv_bfloat162*)&g_Kl[(size_t)rA * Dn + col - 64]);
            split2(acc[nt][2], acc[nt][3],
                   (__nv_bfloat162*)&g_Kh[(size_t)rB * Dn + col - 64],
                   (__nv_bfloat162*)&g_Kl[(size_t)rB * Dn + col - 64]);
        } else if (col == 128) {
            g_u[rA] = acc[nt][0];
            g_u[rB] = acc[nt][2];
        }
    }
}

// ---------------- K2: Z_k = sum_q exp(s_qk - SHIFT); t_k = u_k / Z_k ----------------
__global__ void k_zt() {
    extern __shared__ __nv_bfloat16 sm2[];
    __nv_bfloat16* Ksh = sm2;                    // [64][QKS]
    __nv_bfloat16* Ksl = Ksh + 64 * QKS;
    __nv_bfloat16* Qsh = Ksl + 64 * QKS;         // [128][QKS]
    __nv_bfloat16* Qsl = Qsh + 128 * QKS;
    __shared__ float zred[8 * 64];

    int tid = threadIdx.x;
    int b = blockIdx.y;
    int kg0 = blockIdx.x * 64;

    {
        size_t base = ((size_t)b * Sn + kg0) * Dn;
        const uint32_t* Kgh = (const uint32_t*)&g_Kh[base];
        const uint32_t* Kgl = (const uint32_t*)&g_Kl[base];
        for (int i = tid; i < 64 * 32; i += 256) {
            int row = i >> 5, p = i & 31;
            *(uint32_t*)&Ksh[row * QKS + 2 * p] = Kgh[row * 32 + p];
            *(uint32_t*)&Ksl[row * QKS + 2 * p] = Kgl[row * 32 + p];
        }
    }

    int warp = tid >> 5, lane = tid & 31;
    int g = lane >> 2, t = lane & 3;
    int rw = warp * 16;

    float z0[8], z1[8];
#pragma unroll
    for (int nt = 0; nt < 8; nt++) { z0[nt] = 0.0f; z1[nt] = 0.0f; }

    size_t qbase = (size_t)b * Sn * Dn;
    const uint32_t* Qgh = (const uint32_t*)&g_Qh[qbase];
    const uint32_t* Qgl = (const uint32_t*)&g_Ql[qbase];
    for (int qc = 0; qc < 16; qc++) {
        __syncthreads();
        for (int i = tid; i < 128 * 32; i += 256) {
            int row = i >> 5, p = i & 31;
            *(uint32_t*)&Qsh[row * QKS + 2 * p] = Qgh[(qc * 128 + row) * 32 + p];
            *(uint32_t*)&Qsl[row * QKS + 2 * p] = Qgl[(qc * 128 + row) * 32 + p];
        }
        __syncthreads();

        float acc[8][4];
#pragma unroll
        for (int nt = 0; nt < 8; nt++)
#pragma unroll
            for (int i = 0; i < 4; i++) acc[nt][i] = 0.0f;

#pragma unroll
        for (int ks = 0; ks < 4; ks++) {
            int kb = ks * 16;
            uint32_t ah0 = ld32(&Qsh[(rw + g) * QKS + kb + 2 * t]);
            uint32_t ah1 = ld32(&Qsh[(rw + g + 8) * QKS + kb + 2 * t]);
            uint32_t ah2 = ld32(&Qsh[(rw + g) * QKS + kb + 2 * t + 8]);
            uint32_t ah3 = ld32(&Qsh[(rw + g + 8) * QKS + kb + 2 * t + 8]);
            uint32_t al0 = ld32(&Qsl[(rw + g) * QKS + kb + 2 * t]);
            uint32_t al1 = ld32(&Qsl[(rw + g + 8) * QKS + kb + 2 * t]);
            uint32_t al2 = ld32(&Qsl[(rw + g) * QKS + kb + 2 * t + 8]);
            uint32_t al3 = ld32(&Qsl[(rw + g + 8) * QKS + kb + 2 * t + 8]);
#pragma unroll
            for (int nt = 0; nt < 8; nt++) {
                uint32_t bh0 = ld32(&Ksh[(nt * 8 + g) * QKS + kb + 2 * t]);
                uint32_t bh1 = ld32(&Ksh[(nt * 8 + g) * QKS + kb + 2 * t + 8]);
                uint32_t bl0 = ld32(&Ksl[(nt * 8 + g) * QKS + kb + 2 * t]);
                uint32_t bl1 = ld32(&Ksl[(nt * 8 + g) * QKS + kb + 2 * t + 8]);
                mma_bf16(acc[nt], ah0, ah1, ah2, ah3, bh0, bh1);
                mma_bf16(acc[nt], ah0, ah1, ah2, ah3, bl0, bl1);
                mma_bf16(acc[nt], al0, al1, al2, al3, bh0, bh1);
            }
        }
#pragma unroll
        for (int nt = 0; nt < 8; nt++) {
            z0[nt] += __expf(acc[nt][0] - SHIFT) + __expf(acc[nt][2] - SHIFT);
            z1[nt] += __expf(acc[nt][1] - SHIFT) + __expf(acc[nt][3] - SHIFT);
        }
    }

#pragma unroll
    for (int nt = 0; nt < 8; nt++) {
        z0[nt] += __shfl_xor_sync(0xffffffffu, z0[nt], 4);
        z0[nt] += __shfl_xor_sync(0xffffffffu, z0[nt], 8);
        z0[nt] += __shfl_xor_sync(0xffffffffu, z0[nt], 16);
        z1[nt] += __shfl_xor_sync(0xffffffffu, z1[nt], 4);
        z1[nt] += __shfl_xor_sync(0xffffffffu, z1[nt], 8);
        z1[nt] += __shfl_xor_sync(0xffffffffu, z1[nt], 16);
    }
    if (lane < 4) {
#pragma unroll
        for (int nt = 0; nt < 8; nt++) {
            zred[warp * 64 + nt * 8 + 2 * lane]     = z0[nt];
            zred[warp * 64 + nt * 8 + 2 * lane + 1] = z1[nt];
        }
    }
    __syncthreads();
    if (tid < 64) {
        float Z = 0.0f;
#pragma unroll
        for (int w = 0; w < 8; w++) Z += zred[w * 64 + tid];
        int kg = b * Sn + kg0 + tid;
        g_t[kg] = g_u[kg] / Z;
    }
}

// ---------------- K3: out[b,q] = bf + sum_k exp(s_qk - SHIFT) * t_k ----------------
__global__ void k_out(const float* __restrict__ bfp, float* __restrict__ out) {
    extern __shared__ __nv_bfloat16 sm3[];
    __nv_bfloat16* Qsh = sm3;                    // [128][QKS]
    __nv_bfloat16* Qsl = Qsh + 128 * QKS;
    __nv_bfloat16* Ksh = Qsl + 128 * QKS;        // [64][QKS]
    __nv_bfloat16* Ksl = Ksh + 64 * QKS;
    __shared__ float ts[64];

    int tid = threadIdx.x;
    int b = blockIdx.y;
    int q0 = blockIdx.x * 128;

    {
        size_t base = ((size_t)b * Sn + q0) * Dn;
        const uint32_t* Qgh = (const uint32_t*)&g_Qh[base];
        const uint32_t* Qgl = (const uint32_t*)&g_Ql[base];
        for (int i = tid; i < 128 * 32; i += 256) {
            int row = i >> 5, p = i & 31;
            *(uint32_t*)&Qsh[row * QKS + 2 * p] = Qgh[row * 32 + p];
            *(uint32_t*)&Qsl[row * QKS + 2 * p] = Qgl[row * 32 + p];
        }
    }

    int warp = tid >> 5, lane = tid & 31;
    int g = lane >> 2, t = lane & 3;
    int rw = warp * 16;

    float olo = 0.0f, ohi = 0.0f;

    for (int kc = 0; kc < 32; kc++) {
        __syncthreads();
        size_t base = ((size_t)b * Sn + kc * 64) * Dn;
        const uint32_t* Kgh = (const uint32_t*)&g_Kh[base];
        const uint32_t* Kgl = (const uint32_t*)&g_Kl[base];
        for (int i = tid; i < 64 * 32; i += 256) {
            int row = i >> 5, p = i & 31;
            *(uint32_t*)&Ksh[row * QKS + 2 * p] = Kgh[row * 32 + p];
            *(uint32_t*)&Ksl[row * QKS + 2 * p] = Kgl[row * 32 + p];
        }
        if (tid < 64) ts[tid] = g_t[b * Sn + kc * 64 + tid];
        __syncthreads();

        float acc[8][4];
#pragma unroll
        for (int nt = 0; nt < 8; nt++)
#pragma unroll
            for (int i = 0; i < 4; i++) acc[nt][i] = 0.0f;

#pragma unroll
        for (int ks = 0; ks < 4; ks++) {
            int kb = ks * 16;
            uint32_t ah0 = ld32(&Qsh[(rw + g) * QKS + kb + 2 * t]);
            uint32_t ah1 = ld32(&Qsh[(rw + g + 8) * QKS + kb + 2 * t]);
            uint32_t ah2 = ld32(&Qsh[(rw + g) * QKS + kb + 2 * t + 8]);
            uint32_t ah3 = ld32(&Qsh[(rw + g + 8) * QKS + kb + 2 * t + 8]);
            uint32_t al0 = ld32(&Qsl[(rw + g) * QKS + kb + 2 * t]);
            uint32_t al1 = ld32(&Qsl[(rw + g + 8) * QKS + kb + 2 * t]);
            uint32_t al2 = ld32(&Qsl[(rw + g) * QKS + kb + 2 * t + 8]);
            uint32_t al3 = ld32(&Qsl[(rw + g + 8) * QKS + kb + 2 * t + 8]);
#pragma unroll
            for (int nt = 0; nt < 8; nt++) {
                uint32_t bh0 = ld32(&Ksh[(nt * 8 + g) * QKS + kb + 2 * t]);
                uint32_t bh1 = ld32(&Ksh[(nt * 8 + g) * QKS + kb + 2 * t + 8]);
                uint32_t bl0 = ld32(&Ksl[(nt * 8 + g) * QKS + kb + 2 * t]);
                uint32_t bl1 = ld32(&Ksl[(nt * 8 + g) * QKS + kb + 2 * t + 8]);
                mma_bf16(acc[nt], ah0, ah1, ah2, ah3, bh0, bh1);
                mma_bf16(acc[nt], ah0, ah1, ah2, ah3, bl0, bl1);
                mma_bf16(acc[nt], al0, al1, al2, al3, bh0, bh1);
            }
        }
#pragma unroll
        for (int nt = 0; nt < 8; nt++) {
            float tc0 = ts[nt * 8 + 2 * t];
            float tc1 = ts[nt * 8 + 2 * t + 1];
            olo += __expf(acc[nt][0] - SHIFT) * tc0 + __expf(acc[nt][1] - SHIFT) * tc1;
            ohi += __expf(acc[nt][2] - SHIFT) * tc0 + __expf(acc[nt][3] - SHIFT) * tc1;
        }
    }

    olo += __shfl_xor_sync(0xffffffffu, olo, 1);
    olo += __shfl_xor_sync(0xffffffffu, olo, 2);
    ohi += __shfl_xor_sync(0xffffffffu, ohi, 1);
    ohi += __shfl_xor_sync(0xffffffffu, ohi, 2);

    if (t == 0) {
        float bias = bfp[0];
        out[b * Sn + q0 + rw + g]     = olo + bias;
        out[b * Sn + q0 + rw + g + 8] = ohi + bias;
    }
}

extern "C" void kernel_launch(void* const* d_in, const int* in_sizes, int n_in,
                              void* d_out, int out_size) {
    (void)in_sizes; (void)n_in; (void)out_size;
    const float* x  = (const float*)d_in[0];
    const float* Wq = (const float*)d_in[1];
    const float* Wk = (const float*)d_in[2];
    const float* Wv = (const float*)d_in[3];
    const float* Wf = (const float*)d_in[4];
    const float* bf = (const float*)d_in[5];
    float* out = (float*)d_out;

    const int smem_k1 = (2 * 128 * NPAD + 2 * NPAD * NPAD) * (int)sizeof(__nv_bfloat16);
    const int smem_k2 = (2 * 64 * QKS + 2 * 128 * QKS) * (int)sizeof(__nv_bfloat16);
    const int smem_k3 = smem_k2;
    cudaFuncSetAttribute(k_qku, cudaFuncAttributeMaxDynamicSharedMemorySize, smem_k1);
    cudaFuncSetAttribute(k_zt,  cudaFuncAttributeMaxDynamicSharedMemorySize, smem_k2);
    cudaFuncSetAttribute(k_out, cudaFuncAttributeMaxDynamicSharedMemorySize, smem_k3);

    k_pe<<<(Sn * (Hn / 2) + 255) / 256, 256>>>();
    k_wcat<<<(NPAD * Hn + 255) / 256, 256>>>(Wq, Wk, Wv, Wf);
    k_qku<<<Bn * Sn / 128, 256, smem_k1>>>(x);
    k_zt<<<dim3(Sn / 64, Bn), 256, smem_k2>>>();
    k_out<<<dim3(Sn / 128, Bn), 256, smem_k3>>>(bf, out);
}

// round 6
// speedup vs baseline: 1.1958x; 1.1958x over previous
#include <cuda_runtime.h>
#include <cuda_bf16.h>
#include <cuda_fp16.h>
#include <math.h>
#include <stdint.h>

#define DI __device__ __forceinline__

namespace {
constexpr int Bn = 16;
constexpr int Sn = 2048;
constexpr int Hn = 128;
constexpr int Dn = 64;
constexpr float SHIFT = 8.0f;       // small shift; E stored in fp16, clamped
constexpr float ECLAMP = 60000.0f;  // < fp16 max
constexpr int NPAD = 136;           // padded n-dim (64 Q | 64 K | u | pad)
constexpr int QKS = 72;             // smem stride for 64-wide bf16 tiles
constexpr int ES = 136;             // smem stride (halves) for E tile, 16B-aligned rows
}

// Scratch (no device mallocs allowed)
__device__ __nv_bfloat16 g_Wh[NPAD * Hn];
__device__ __nv_bfloat16 g_Wl[NPAD * Hn];
__device__ float         g_PE[Sn * Hn];
__device__ __nv_bfloat16 g_Qh[Bn * Sn * Dn];
__device__ __nv_bfloat16 g_Ql[Bn * Sn * Dn];
__device__ __nv_bfloat16 g_Kh[Bn * Sn * Dn];
__device__ __nv_bfloat16 g_Kl[Bn * Sn * Dn];
__device__ float         g_u[Bn * Sn];
__device__ float         g_t[Bn * Sn];
__device__ __half        g_E[(size_t)Bn * Sn * Sn];   // 134MB: exp(s-SHIFT) fp16

DI uint32_t ld32(const __nv_bfloat16* p) { return *(const uint32_t*)p; }

DI void mma_bf16(float* c, uint32_t a0, uint32_t a1, uint32_t a2, uint32_t a3,
                 uint32_t b0, uint32_t b1) {
    asm volatile(
        "mma.sync.aligned.m16n8k16.row.col.f32.bf16.bf16.f32 "
        "{%0,%1,%2,%3}, {%4,%5,%6,%7}, {%8,%9}, {%0,%1,%2,%3};\n"
        : "+f"(c[0]), "+f"(c[1]), "+f"(c[2]), "+f"(c[3])
        : "r"(a0), "r"(a1), "r"(a2), "r"(a3), "r"(b0), "r"(b1));
}

DI void split2(float a, float b, __nv_bfloat162* hd, __nv_bfloat162* ld) {
    __nv_bfloat162 h = __floats2bfloat162_rn(a, b);
    float ra = a - __low2float(h);
    float rb = b - __high2float(h);
    *hd = h;
    *ld = __floats2bfloat162_rn(ra, rb);
}

// ---------------- K0a: positional encoding ----------------
__global__ void k_pe() {
    int idx = blockIdx.x * blockDim.x + threadIdx.x;
    if (idx >= Sn * (Hn / 2)) return;
    int p = idx >> 6;
    int j = idx & 63;
    double fac = pow(10000.0, (double)j / 64.0);
    float ang = (float)((double)p / fac);
    float sv, cv;
    sincosf(ang, &sv, &cv);
    g_PE[p * Hn + 2 * j]     = sv;
    g_PE[p * Hn + 2 * j + 1] = cv;
}

// ---------------- K0b: fused transposed weight, hi/lo ----------------
__global__ void k_wcat(const float* __restrict__ Wq, const float* __restrict__ Wk,
                       const float* __restrict__ Wv, const float* __restrict__ Wf) {
    int idx = blockIdx.x * blockDim.x + threadIdx.x;
    if (idx >= NPAD * Hn) return;
    int n = idx >> 7;
    int h = idx & 127;
    float v = 0.0f;
    if (n < 64) {
        v = Wq[h * Dn + n] * 0.125f;
    } else if (n < 128) {
        v = Wk[h * Dn + (n - 64)];
    } else if (n == 128) {
        float s = 0.0f;
        for (int d = 0; d < Dn; ++d) s += Wv[h * Dn + d] * Wf[d];
        v = s;
    }
    __nv_bfloat16 hb = __float2bfloat16(v);
    g_Wh[n * Hn + h] = hb;
    g_Wl[n * Hn + h] = __float2bfloat16(v - __bfloat162float(hb));
}

// ---------------- K1: xp = x + PE; Q,K (hi/lo) and u ----------------
__global__ void k_qku(const float* __restrict__ x) {
    extern __shared__ __nv_bfloat16 sm[];
    __nv_bfloat16* Ash = sm;
    __nv_bfloat16* Asl = Ash + 128 * NPAD;
    __nv_bfloat16* Bsh = Asl + 128 * NPAD;
    __nv_bfloat16* Bsl = Bsh + NPAD * NPAD;

    int tid = threadIdx.x;
    int r0 = blockIdx.x * 128;
    int srow0 = r0 & (Sn - 1);

    const float4* x4 = (const float4*)x;
    for (int i = tid; i < 128 * 32; i += 256) {
        int row = i >> 5, c4 = i & 31;
        float4 v = x4[(size_t)(r0 + row) * 32 + c4];
        const float* pe = &g_PE[(srow0 + row) * Hn + c4 * 4];
        v.x += pe[0]; v.y += pe[1]; v.z += pe[2]; v.w += pe[3];
        __nv_bfloat162* dh = (__nv_bfloat162*)&Ash[row * NPAD + c4 * 4];
        __nv_bfloat162* dl = (__nv_bfloat162*)&Asl[row * NPAD + c4 * 4];
        split2(v.x, v.y, &dh[0], &dl[0]);
        split2(v.z, v.w, &dh[1], &dl[1]);
    }
    for (int i = tid; i < NPAD * Hn; i += 256) {
        int n = i >> 7, h = i & 127;
        Bsh[n * NPAD + h] = g_Wh[i];
        Bsl[n * NPAD + h] = g_Wl[i];
    }
    __syncthreads();

    int warp = tid >> 5, lane = tid & 31;
    int g = lane >> 2, t = lane & 3;
    int rw = warp * 16;

    float acc[17][4];
#pragma unroll
    for (int nt = 0; nt < 17; nt++)
#pragma unroll
        for (int i = 0; i < 4; i++) acc[nt][i] = 0.0f;

#pragma unroll
    for (int ks = 0; ks < 8; ks++) {
        int kb = ks * 16;
        uint32_t ah0 = ld32(&Ash[(rw + g) * NPAD + kb + 2 * t]);
        uint32_t ah1 = ld32(&Ash[(rw + g + 8) * NPAD + kb + 2 * t]);
        uint32_t ah2 = ld32(&Ash[(rw + g) * NPAD + kb + 2 * t + 8]);
        uint32_t ah3 = ld32(&Ash[(rw + g + 8) * NPAD + kb + 2 * t + 8]);
        uint32_t al0 = ld32(&Asl[(rw + g) * NPAD + kb + 2 * t]);
        uint32_t al1 = ld32(&Asl[(rw + g + 8) * NPAD + kb + 2 * t]);
        uint32_t al2 = ld32(&Asl[(rw + g) * NPAD + kb + 2 * t + 8]);
        uint32_t al3 = ld32(&Asl[(rw + g + 8) * NPAD + kb + 2 * t + 8]);
#pragma unroll
        for (int nt = 0; nt < 17; nt++) {
            uint32_t bh0 = ld32(&Bsh[(nt * 8 + g) * NPAD + kb + 2 * t]);
            uint32_t bh1 = ld32(&Bsh[(nt * 8 + g) * NPAD + kb + 2 * t + 8]);
            uint32_t bl0 = ld32(&Bsl[(nt * 8 + g) * NPAD + kb + 2 * t]);
            uint32_t bl1 = ld32(&Bsl[(nt * 8 + g) * NPAD + kb + 2 * t + 8]);
            mma_bf16(acc[nt], ah0, ah1, ah2, ah3, bh0, bh1);
            mma_bf16(acc[nt], ah0, ah1, ah2, ah3, bl0, bl1);
            mma_bf16(acc[nt], al0, al1, al2, al3, bh0, bh1);
        }
    }

    int rA = r0 + rw + g, rB = rA + 8;
#pragma unroll
    for (int nt = 0; nt < 17; nt++) {
        int col = nt * 8 + 2 * t;
        if (col < 64) {
            split2(acc[nt][0], acc[nt][1],
                   (__nv_bfloat162*)&g_Qh[(size_t)rA * Dn + col],
                   (__nv_bfloat162*)&g_Ql[(size_t)rA * Dn + col]);
            split2(acc[nt][2], acc[nt][3],
                   (__nv_bfloat162*)&g_Qh[(size_t)rB * Dn + col],
                   (__nv_bfloat162*)&g_Ql[(size_t)rB * Dn + col]);
        } else if (col < 128) {
            split2(acc[nt][0], acc[nt][1],
                   (__nv_bfloat162*)&g_Kh[(size_t)rA * Dn + col - 64],
                   (__nv_bfloat162*)&g_Kl[(size_t)rA * Dn + col - 64]);
            split2(acc[nt][2], acc[nt][3],
                   (__nv_bfloat162*)&g_Kh[(size_t)rB * Dn + col - 64],
                   (__nv_bfloat162*)&g_Kl[(size_t)rB * Dn + col - 64]);
        } else if (col == 128) {
            g_u[rA] = acc[nt][0];
            g_u[rB] = acc[nt][2];
        }
    }
}

// ---------------- K2: scores once; E to gmem (fp16); Z from rounded E; t = u/Z ----------------
// CTA: 128 k-cols x (all 2048 q). Grid 16x16 = 256 CTAs -> single wave @ 2 CTA/SM.
__global__ __launch_bounds__(256, 2) void k_zt2() {
    extern __shared__ __nv_bfloat16 sm2[];
    __nv_bfloat16* Ksh = sm2;                    // [128][QKS]
    __nv_bfloat16* Ksl = Ksh + 128 * QKS;
    __nv_bfloat16* Qsh = Ksl + 128 * QKS;        // [128][QKS]
    __nv_bfloat16* Qsl = Qsh + 128 * QKS;
    __half*        Es  = (__half*)(Qsl + 128 * QKS);   // [128][ES]
    __shared__ float zred[8 * 128];

    int tid = threadIdx.x;
    int b = blockIdx.y;
    int kg0 = blockIdx.x * 128;

    {
        size_t base = ((size_t)b * Sn + kg0) * Dn;
        const uint32_t* Kgh = (const uint32_t*)&g_Kh[base];
        const uint32_t* Kgl = (const uint32_t*)&g_Kl[base];
        for (int i = tid; i < 128 * 32; i += 256) {
            int row = i >> 5, p = i & 31;
            *(uint32_t*)&Ksh[row * QKS + 2 * p] = Kgh[row * 32 + p];
            *(uint32_t*)&Ksl[row * QKS + 2 * p] = Kgl[row * 32 + p];
        }
    }

    int warp = tid >> 5, lane = tid & 31;
    int g = lane >> 2, t = lane & 3;
    int rw = warp * 16;

    float z0[16], z1[16];
#pragma unroll
    for (int nt = 0; nt < 16; nt++) { z0[nt] = 0.0f; z1[nt] = 0.0f; }

    size_t qbase = (size_t)b * Sn * Dn;
    const uint32_t* Qgh = (const uint32_t*)&g_Qh[qbase];
    const uint32_t* Qgl = (const uint32_t*)&g_Ql[qbase];

    for (int qc = 0; qc < 16; qc++) {
        __syncthreads();          // protect Qs (prev mma) and Es (prev gmem drain)
        for (int i = tid; i < 128 * 32; i += 256) {
            int row = i >> 5, p = i & 31;
            *(uint32_t*)&Qsh[row * QKS + 2 * p] = Qgh[(qc * 128 + row) * 32 + p];
            *(uint32_t*)&Qsl[row * QKS + 2 * p] = Qgl[(qc * 128 + row) * 32 + p];
        }
        __syncthreads();

        float acc[16][4];
#pragma unroll
        for (int nt = 0; nt < 16; nt++)
#pragma unroll
            for (int i = 0; i < 4; i++) acc[nt][i] = 0.0f;

#pragma unroll
        for (int ks = 0; ks < 4; ks++) {
            int kb = ks * 16;
            uint32_t ah0 = ld32(&Qsh[(rw + g) * QKS + kb + 2 * t]);
            uint32_t ah1 = ld32(&Qsh[(rw + g + 8) * QKS + kb + 2 * t]);
            uint32_t ah2 = ld32(&Qsh[(rw + g) * QKS + kb + 2 * t + 8]);
            uint32_t ah3 = ld32(&Qsh[(rw + g + 8) * QKS + kb + 2 * t + 8]);
            uint32_t al0 = ld32(&Qsl[(rw + g) * QKS + kb + 2 * t]);
            uint32_t al1 = ld32(&Qsl[(rw + g + 8) * QKS + kb + 2 * t]);
            uint32_t al2 = ld32(&Qsl[(rw + g) * QKS + kb + 2 * t + 8]);
            uint32_t al3 = ld32(&Qsl[(rw + g + 8) * QKS + kb + 2 * t + 8]);
#pragma unroll
            for (int nt = 0; nt < 16; nt++) {
                uint32_t bh0 = ld32(&Ksh[(nt * 8 + g) * QKS + kb + 2 * t]);
                uint32_t bh1 = ld32(&Ksh[(nt * 8 + g) * QKS + kb + 2 * t + 8]);
                uint32_t bl0 = ld32(&Ksl[(nt * 8 + g) * QKS + kb + 2 * t]);
                uint32_t bl1 = ld32(&Ksl[(nt * 8 + g) * QKS + kb + 2 * t + 8]);
                mma_bf16(acc[nt], ah0, ah1, ah2, ah3, bh0, bh1);
                mma_bf16(acc[nt], ah0, ah1, ah2, ah3, bl0, bl1);
                mma_bf16(acc[nt], al0, al1, al2, al3, bh0, bh1);
            }
        }

        int rA = rw + g, rB = rA + 8;
#pragma unroll
        for (int nt = 0; nt < 16; nt++) {
            int c0 = nt * 8 + 2 * t;
            float e0 = fminf(__expf(acc[nt][0] - SHIFT), ECLAMP);
            float e1 = fminf(__expf(acc[nt][1] - SHIFT), ECLAMP);
            float e2 = fminf(__expf(acc[nt][2] - SHIFT), ECLAMP);
            float e3 = fminf(__expf(acc[nt][3] - SHIFT), ECLAMP);
            __half2 h01 = __floats2half2_rn(e0, e1);
            __half2 h23 = __floats2half2_rn(e2, e3);
            *(__half2*)&Es[rA * ES + c0] = h01;
            *(__half2*)&Es[rB * ES + c0] = h23;
            // Z from the SAME rounded values -> column softmax self-consistent
            float2 f01 = __half22float2(h01);
            float2 f23 = __half22float2(h23);
            z0[nt] += f01.x + f23.x;
            z1[nt] += f01.y + f23.y;
        }
        __syncthreads();

        // coalesced E tile -> gmem: 128 rows x 256B
        size_t grow = (size_t)(b * Sn + qc * 128) * Sn + kg0;
#pragma unroll
        for (int j = 0; j < 8; j++) {
            int flat = tid + 256 * j;
            int r = flat >> 4, seg = flat & 15;
            uint4 v = *(const uint4*)&Es[r * ES + seg * 8];
            *(uint4*)&g_E[grow + (size_t)r * Sn + seg * 8] = v;
        }
    }

#pragma unroll
    for (int nt = 0; nt < 16; nt++) {
        z0[nt] += __shfl_xor_sync(0xffffffffu, z0[nt], 4);
        z0[nt] += __shfl_xor_sync(0xffffffffu, z0[nt], 8);
        z0[nt] += __shfl_xor_sync(0xffffffffu, z0[nt], 16);
        z1[nt] += __shfl_xor_sync(0xffffffffu, z1[nt], 4);
        z1[nt] += __shfl_xor_sync(0xffffffffu, z1[nt], 8);
        z1[nt] += __shfl_xor_sync(0xffffffffu, z1[nt], 16);
    }
    if (lane < 4) {
#pragma unroll
        for (int nt = 0; nt < 16; nt++) {
            zred[warp * 128 + nt * 8 + 2 * lane]     = z0[nt];
            zred[warp * 128 + nt * 8 + 2 * lane + 1] = z1[nt];
        }
    }
    __syncthreads();
    if (tid < 128) {
        float Z = 0.0f;
#pragma unroll
        for (int w = 0; w < 8; w++) Z += zred[w * 128 + tid];
        int kg = b * Sn + kg0 + tid;
        g_t[kg] = g_u[kg] / Z;
    }
}

// ---------------- K3: memory-bound GEMV  out[b,q] = bf + E[b,q,:] . t[b,:] ----------------
__global__ void k_gemv(const float* __restrict__ bfp, float* __restrict__ out) {
    __shared__ float ts[Sn];
    int tid = threadIdx.x;
    int b = blockIdx.y;
    int q0 = blockIdx.x * 32;

    for (int i = tid; i < Sn; i += 256) ts[i] = g_t[b * Sn + i];
    __syncthreads();

    int warp = tid >> 5, lane = tid & 31;
    float bias = bfp[0];

#pragma unroll
    for (int rr = 0; rr < 4; rr++) {
        int q = q0 + warp * 4 + rr;
        const uint4* Erow = (const uint4*)&g_E[((size_t)b * Sn + q) * Sn];
        float acc = 0.0f;
#pragma unroll
        for (int j = 0; j < 8; j++) {
            uint4 v = Erow[j * 32 + lane];
            const float2* tp = (const float2*)&ts[j * 256 + lane * 8];
            float2 f, tt;
            f = __half22float2(*(__half2*)&v.x); tt = tp[0]; acc += f.x * tt.x + f.y * tt.y;
            f = __half22float2(*(__half2*)&v.y); tt = tp[1]; acc += f.x * tt.x + f.y * tt.y;
            f = __half22float2(*(__half2*)&v.z); tt = tp[2]; acc += f.x * tt.x + f.y * tt.y;
            f = __half22float2(*(__half2*)&v.w); tt = tp[3]; acc += f.x * tt.x + f.y * tt.y;
        }
        acc += __shfl_xor_sync(0xffffffffu, acc, 16);
        acc += __shfl_xor_sync(0xffffffffu, acc, 8);
        acc += __shfl_xor_sync(0xffffffffu, acc, 4);
        acc += __shfl_xor_sync(0xffffffffu, acc, 2);
        acc += __shfl_xor_sync(0xffffffffu, acc, 1);
        if (lane == 0) out[b * Sn + q] = acc + bias;
    }
}

extern "C" void kernel_launch(void* const* d_in, const int* in_sizes, int n_in,
                              void* d_out, int out_size) {
    (void)in_sizes; (void)n_in; (void)out_size;
    const float* x  = (const float*)d_in[0];
    const float* Wq = (const float*)d_in[1];
    const float* Wk = (const float*)d_in[2];
    const float* Wv = (const float*)d_in[3];
    const float* Wf = (const float*)d_in[4];
    const float* bf = (const float*)d_in[5];
    float* out = (float*)d_out;

    const int smem_k1 = (2 * 128 * NPAD + 2 * NPAD * NPAD) * (int)sizeof(__nv_bfloat16);
    const int smem_k2 = 4 * 128 * QKS * (int)sizeof(__nv_bfloat16)
                      + 128 * ES * (int)sizeof(__half);
    cudaFuncSetAttribute(k_qku, cudaFuncAttributeMaxDynamicSharedMemorySize, smem_k1);
    cudaFuncSetAttribute(k_zt2, cudaFuncAttributeMaxDynamicSharedMemorySize, smem_k2);

    k_pe<<<(Sn * (Hn / 2) + 255) / 256, 256>>>();
    k_wcat<<<(NPAD * Hn + 255) / 256, 256>>>(Wq, Wk, Wv, Wf);
    k_qku<<<Bn * Sn / 128, 256, smem_k1>>>(x);
    k_zt2<<<dim3(Sn / 128, Bn), 256, smem_k2>>>();
    k_gemv<<<dim3(Sn / 32, Bn), 256>>>(bf, out);
}